// round 5
// baseline (speedup 1.0000x reference)
#include <cuda_runtime.h>
#include <cuda_bf16.h>
#include <cstdint>

// Fixed shapes for LengthRegulator_82274393523030:
//   x:        (B=32, T=512, C=384) float32
//   duration: (B=32, T=512)        int64 (or int32 if JAX x64 disabled — detected at runtime)
//   max_len:  4096
// Output: out (32, 4096, 384) float32, then mel_len (32,) appended (layout inferred from out_size).

#define B_  32
#define T_  512
#define C_  384
#define ML_ 4096
#define C4_ (C_ / 4)          // 96 float4 per row

// Scratch: index map per (batch, output position). -1 => masked (write zeros).
__device__ int g_idx[B_ * ML_];

// ---------------------------------------------------------------------------
// Kernel 1: per-batch cumsum + searchsorted index map + mel_len tail write.
// grid = B_, block = T_ (512 threads).
// mel_mode: 0 = don't write mel_len, 1 = write as float32 tail, 2 = write as int64 tail.
// ---------------------------------------------------------------------------
__global__ void __launch_bounds__(T_) lr_scan_kernel(const void* __restrict__ dur_raw,
                                                     float* __restrict__ out,
                                                     int mel_mode) {
    __shared__ int s_csum[T_];
    __shared__ int s_flag;   // nonzero => some odd int32 word nonzero => duration is int32

    const int t = threadIdx.x;
    const int b = blockIdx.x;

    // --- runtime int64-vs-int32 detection on the first 1024 int32 words ---
    if (t == 0) s_flag = 0;
    __syncthreads();
    {
        const int* w = (const int*)dur_raw;
        if (w[2 * t + 1] != 0) s_flag = 1;   // benign race
    }
    __syncthreads();
    const bool is64 = (s_flag == 0);

    // --- load duration (clamped at 0) ---
    long long dv;
    if (is64) dv = ((const long long*)dur_raw)[(size_t)b * T_ + t];
    else      dv = (long long)((const int*)dur_raw)[(size_t)b * T_ + t];
    int d = dv > 0 ? (int)dv : 0;

    // --- inclusive scan (Hillis-Steele) ---
    s_csum[t] = d;
    __syncthreads();
    #pragma unroll
    for (int off = 1; off < T_; off <<= 1) {
        int v = s_csum[t];
        int add = (t >= off) ? s_csum[t - off] : 0;
        __syncthreads();
        s_csum[t] = v + add;
        __syncthreads();
    }

    const int mel = s_csum[T_ - 1];

    // --- mel_len tail ---
    if (t == 0) {
        const size_t total = (size_t)B_ * ML_ * C_;
        if (mel_mode == 1) {
            out[total + b] = (float)mel;
        } else if (mel_mode == 2) {
            ((long long*)(out + total))[b] = (long long)mel;
        }
    }

    // --- searchsorted(csum, p, side='right') for 8 positions per thread ---
    #pragma unroll
    for (int k = 0; k < ML_ / T_; ++k) {
        int p = t + k * T_;
        int v;
        if (p >= mel) {
            v = -1;                       // masked -> zeros
        } else {
            int lo = 0, hi = T_;
            while (lo < hi) {             // first i with csum[i] > p
                int mid = (lo + hi) >> 1;
                if (s_csum[mid] <= p) lo = mid + 1; else hi = mid;
            }
            v = lo < (T_ - 1) ? lo : (T_ - 1);   // clip (p<mel => lo<=T_-1 anyway)
        }
        g_idx[b * ML_ + p] = v;
    }
}

// ---------------------------------------------------------------------------
// Kernel 2: gather-expand copy. One float4 per thread.
// block = (96, 4): x = float4 column, y = position within block's 4 rows.
// grid  = B_*ML_/4 blocks.
// ---------------------------------------------------------------------------
__global__ void __launch_bounds__(C4_ * 4) lr_expand_kernel(const float4* __restrict__ x,
                                                            float4* __restrict__ out) {
    const int row = blockIdx.x * 4 + threadIdx.y;   // global (b*ML + p)
    const int c4  = threadIdx.x;                    // 0..95
    const int idx = g_idx[row];                     // warp-broadcast L1 hit
    const int b   = row >> 12;                      // row / ML_

    float4 v;
    if (idx >= 0) {
        v = __ldg(&x[((size_t)b * T_ + idx) * C4_ + c4]);
    } else {
        v = make_float4(0.f, 0.f, 0.f, 0.f);
    }
    out[(size_t)row * C4_ + c4] = v;                // fully coalesced 1536B/row
}

// ---------------------------------------------------------------------------
extern "C" void kernel_launch(void* const* d_in, const int* in_sizes, int n_in,
                              void* d_out, int out_size) {
    const float* x   = (const float*)d_in[0];
    const void*  dur = d_in[1];
    float* out = (float*)d_out;

    // Infer how mel_len is packed after the main tensor.
    const long long total = (long long)B_ * ML_ * C_;
    const long long extra = (long long)out_size - total;
    int mel_mode = 0;
    if (extra == B_)          mel_mode = 1;   // float32 tail
    else if (extra == 2 * B_) mel_mode = 2;   // raw int64 tail (2 float slots each)

    lr_scan_kernel<<<B_, T_>>>(dur, out, mel_mode);

    dim3 blk(C4_, 4);
    lr_expand_kernel<<<(B_ * ML_) / 4, blk>>>((const float4*)x, (float4*)out);
}

// round 6
// speedup vs baseline: 1.4570x; 1.4570x over previous
#include <cuda_runtime.h>
#include <cuda_bf16.h>
#include <cstdint>

// LengthRegulator: x (32,512,384) f32, duration (32,512) int64/int32, max_len=4096.
// out = (32,4096,384) f32 gather-expand + mel_len tail.

#define B_  32
#define T_  512
#define C_  384
#define ML_ 4096
#define C4_ (C_ / 4)           // 96 float4 per row
#define RPB 16                 // rows per expand block
#define UNR 4                  // unroll depth (RPB / blockDim.y)

// Scratch: input-row index per (batch, output position). -1 => masked (zeros).
__device__ int g_idx[B_ * ML_];

// ---------------------------------------------------------------------------
// Kernel 1: per-batch cumsum (shuffle scan) + searchsorted index map + mel_len.
// grid = B_, block = T_ (512 threads = 16 warps).
// ---------------------------------------------------------------------------
__global__ void __launch_bounds__(T_) lr_scan_kernel(const void* __restrict__ dur_raw,
                                                     float* __restrict__ out,
                                                     int mel_mode) {
    __shared__ int s_csum[T_];
    __shared__ int s_wsum[16];
    __shared__ int s_flag;

    const int t    = threadIdx.x;
    const int b    = blockIdx.x;
    const int lane = t & 31;
    const int wid  = t >> 5;

    // --- runtime int64-vs-int32 detection (odd int32 words all zero => int64) ---
    if (t == 0) s_flag = 0;
    __syncthreads();
    {
        const int* w = (const int*)dur_raw;
        if (w[2 * t + 1] != 0) s_flag = 1;   // benign race
    }
    __syncthreads();
    const bool is64 = (s_flag == 0);

    long long dv;
    if (is64) dv = ((const long long*)dur_raw)[(size_t)b * T_ + t];
    else      dv = (long long)((const int*)dur_raw)[(size_t)b * T_ + t];
    int v = dv > 0 ? (int)dv : 0;

    // --- warp inclusive scan ---
    #pragma unroll
    for (int off = 1; off < 32; off <<= 1) {
        int n = __shfl_up_sync(0xffffffffu, v, off);
        if (lane >= off) v += n;
    }
    if (lane == 31) s_wsum[wid] = v;
    __syncthreads();

    // --- scan the 16 warp totals (warp 0) ---
    if (wid == 0) {
        int wv = (lane < 16) ? s_wsum[lane] : 0;
        #pragma unroll
        for (int off = 1; off < 16; off <<= 1) {
            int n = __shfl_up_sync(0xffffffffu, wv, off);
            if (lane >= off) wv += n;
        }
        if (lane < 16) s_wsum[lane] = wv;
    }
    __syncthreads();

    if (wid > 0) v += s_wsum[wid - 1];
    s_csum[t] = v;
    __syncthreads();

    const int mel = s_csum[T_ - 1];

    if (t == 0) {
        const size_t total = (size_t)B_ * ML_ * C_;
        if (mel_mode == 1)      out[total + b] = (float)mel;
        else if (mel_mode == 2) ((long long*)(out + total))[b] = (long long)mel;
    }

    // --- searchsorted(csum, p, side='right'), 8 positions per thread ---
    #pragma unroll
    for (int k = 0; k < ML_ / T_; ++k) {
        int p = t + k * T_;
        int r;
        if (p >= mel) {
            r = -1;
        } else {
            int lo = 0, hi = T_;
            while (lo < hi) {               // first i with csum[i] > p
                int mid = (lo + hi) >> 1;
                if (s_csum[mid] <= p) lo = mid + 1; else hi = mid;
            }
            r = lo < (T_ - 1) ? lo : (T_ - 1);
        }
        g_idx[b * ML_ + p] = r;
    }
}

// ---------------------------------------------------------------------------
// Kernel 2: gather-expand. Block (96,4) handles 16 rows, 4-deep unroll
// per thread for MLP. Warp-uniform g_idx loads (broadcast).
// grid = B_*ML_/RPB = 8192 blocks.
// ---------------------------------------------------------------------------
__global__ void __launch_bounds__(C4_ * 4) lr_expand_kernel(const float4* __restrict__ x,
                                                            float4* __restrict__ out) {
    const int c4      = threadIdx.x;                       // 0..95
    const int ty      = threadIdx.y;                       // 0..3
    const int rowBase = blockIdx.x * RPB + ty;             // this thread's rows: rowBase + 4*k
    const int b       = (blockIdx.x * RPB) >> 12;          // batch constant per block (RPB | ML_)

    int idx[UNR];
    #pragma unroll
    for (int k = 0; k < UNR; ++k)
        idx[k] = g_idx[rowBase + 4 * k];                   // 4 independent, warp-uniform LDGs

    float4 v[UNR];
    #pragma unroll
    for (int k = 0; k < UNR; ++k) {
        if (idx[k] >= 0)
            v[k] = __ldg(&x[((size_t)b * T_ + idx[k]) * C4_ + c4]);
        else
            v[k] = make_float4(0.f, 0.f, 0.f, 0.f);
    }

    #pragma unroll
    for (int k = 0; k < UNR; ++k)
        out[(size_t)(rowBase + 4 * k) * C4_ + c4] = v[k];  // coalesced 1536 B per row
}

// ---------------------------------------------------------------------------
extern "C" void kernel_launch(void* const* d_in, const int* in_sizes, int n_in,
                              void* d_out, int out_size) {
    const float* x   = (const float*)d_in[0];
    const void*  dur = d_in[1];
    float* out = (float*)d_out;

    const long long total = (long long)B_ * ML_ * C_;
    const long long extra = (long long)out_size - total;
    int mel_mode = 0;
    if (extra == B_)          mel_mode = 1;   // float32 tail
    else if (extra == 2 * B_) mel_mode = 2;   // raw int64 tail

    lr_scan_kernel<<<B_, T_>>>(dur, out, mel_mode);

    dim3 blk(C4_, 4);
    lr_expand_kernel<<<(B_ * ML_) / RPB, blk>>>((const float4*)x, (float4*)out);
}